// round 4
// baseline (speedup 1.0000x reference)
#include <cuda_runtime.h>

#define B 64
#define C 1501
#define D 2048
#define D4 (D / 4)          // 512 float4 per row
#define TOT4 (C * D4)       // 768512 float4 per [C,D] tile
#define ALPHA 0.01f
#define EPS 1e-7f

// Fully fused, one block per memory row c (512 threads, one float4 each).
// Restructured so the register-heavy epilogue (EMA + block-reduce + normalize)
// runs BEFORE the 64-way streaming store loop; the long loop keeps only
// {v, base address, stride} live, letting 3 blocks/SM fit (75% occupancy)
// for more outstanding DRAM writes.
__global__ __launch_bounds__(512, 3) void fused_kernel(
    const float4* __restrict__ x4,
    const float4* __restrict__ mem4,
    const int* __restrict__ cls_raw,
    float4* __restrict__ sel4,
    float4* __restrict__ rep4,
    float4* __restrict__ nm4) {
    const int c = blockIdx.x;
    const int t = threadIdx.x;  // 0..511

    __shared__ int s_cls[B];
    __shared__ int s_is64;
    __shared__ float s_red[16];

    if (t == 0) {
        // int64 little-endian: odd words within the first 64 are high halves
        // of cls[0..31], all zero since 0 <= cls < 1501. int32: random ids.
        int any = 0;
#pragma unroll
        for (int i = 1; i < B; i += 2) any |= cls_raw[i];
        s_is64 = (any == 0) ? 1 : 0;
    }
    __syncthreads();
    if (t < B) s_cls[t] = s_is64 ? cls_raw[2 * t] : cls_raw[t];
    __syncthreads();

    const size_t row_off = (size_t)c * D4 + t;
    const float4 m = __ldg(mem4 + row_off);

    // Owner scan + selected gather (m is the ORIGINAL memory row).
    int ow = -1;
#pragma unroll
    for (int b = 0; b < B; b++) {
        if (s_cls[b] == c) {
            ow = b;                       // max b wins (last write wins)
            sel4[(size_t)b * D4 + t] = m; // selected[b] = memory[cls[b]]
        }
    }

    const float4 v = (ow >= 0) ? __ldg(x4 + (size_t)ow * D4 + t) : m;

    // EMA + L2 normalize for new_mem[c] FIRST (shrinks live set for the loop).
    {
        float4 y;
        y.x = m.x * (1.f - ALPHA) + v.x * ALPHA;
        y.y = m.y * (1.f - ALPHA) + v.y * ALPHA;
        y.z = m.z * (1.f - ALPHA) + v.z * ALPHA;
        y.w = m.w * (1.f - ALPHA) + v.w * ALPHA;
        float ss = y.x * y.x + y.y * y.y + y.z * y.z + y.w * y.w;

#pragma unroll
        for (int off = 16; off > 0; off >>= 1)
            ss += __shfl_xor_sync(0xffffffffu, ss, off);
        if ((t & 31) == 0) s_red[t >> 5] = ss;
        __syncthreads();
        if (t < 32) {
            float u = (t < 16) ? s_red[t] : 0.f;
#pragma unroll
            for (int off = 8; off > 0; off >>= 1)
                u += __shfl_xor_sync(0xffffffffu, u, off);
            if (t == 0) s_red[0] = u;
        }
        __syncthreads();

        const float inv = 1.f / (sqrtf(s_red[0]) + EPS);
        y.x *= inv; y.y *= inv; y.z *= inv; y.w *= inv;
        nm4[row_off] = y;
    }

    // 787 MB streaming writes: tmp_repeated[b, c, :] = v for all b.
    float4* dst = rep4 + row_off;
#pragma unroll 8
    for (int b = 0; b < B; b++) {
        __stcs(dst, v);
        dst += TOT4;
    }
}

extern "C" void kernel_launch(void* const* d_in, const int* in_sizes, int n_in,
                              void* d_out, int out_size) {
    const float* x = (const float*)d_in[0];
    const int* cls = (const int*)d_in[1];
    const float* memory = (const float*)d_in[2];
    float* out = (float*)d_out;

    float* sel = out;                    // [B, D]
    float* rep = out + (size_t)B * D;    // [B, C, D]
    float* nm = rep + (size_t)B * C * D; // [C, D]

    fused_kernel<<<C, 512>>>((const float4*)x, (const float4*)memory, cls,
                             (float4*)sel, (float4*)rep, (float4*)nm);
}

// round 6
// speedup vs baseline: 1.0256x; 1.0256x over previous
#include <cuda_runtime.h>

#define B 64
#define BH 32               // b's per block (split across blockIdx.y)
#define C 1501
#define D 2048
#define D4 (D / 4)          // 512 float4 per row
#define TOT4 (C * D4)       // 768512 float4 per [C,D] tile
#define ALPHA 0.01f
#define EPS 1e-7f

// One block per (memory row c, half of the B repeat copies).
// grid = (C, 2): finer work granularity -> 20.3 waves instead of 10.1,
// halving the tail-wave DRAM starvation.
// y==0 block additionally computes selected[] rows and the EMA+normalized
// new_mem row (epilogue AFTER the store stream, R2 ordering).
__global__ __launch_bounds__(512) void fused_kernel(
    const float4* __restrict__ x4,
    const float4* __restrict__ mem4,
    const int* __restrict__ cls_raw,
    float4* __restrict__ sel4,
    float4* __restrict__ rep4,
    float4* __restrict__ nm4) {
    const int c = blockIdx.x;
    const int half = blockIdx.y;       // 0 or 1
    const int t = threadIdx.x;         // 0..511

    __shared__ int s_cls[B];
    __shared__ int s_is64;
    __shared__ float s_red[16];

    if (t == 0) {
        // int64 little-endian: odd words within the first 64 are high halves
        // of cls[0..31], all zero since 0 <= cls < 1501. int32: random ids.
        int any = 0;
#pragma unroll
        for (int i = 1; i < B; i += 2) any |= cls_raw[i];
        s_is64 = (any == 0) ? 1 : 0;
    }
    __syncthreads();
    if (t < B) s_cls[t] = s_is64 ? cls_raw[2 * t] : cls_raw[t];
    __syncthreads();

    const size_t row_off = (size_t)c * D4 + t;
    const float4 m = __ldg(mem4 + row_off);

    // Owner scan (last write wins -> max b). Only the y==0 block writes
    // selected[b] (original memory row: gather-before-scatter semantics).
    int ow = -1;
#pragma unroll
    for (int b = 0; b < B; b++) {
        if (s_cls[b] == c) {
            ow = b;
            if (half == 0) sel4[(size_t)b * D4 + t] = m;
        }
    }

    const float4 v = (ow >= 0) ? __ldg(x4 + (size_t)ow * D4 + t) : m;

    // Streaming writes: this block's BH copies of tmp_memory[c].
    float4* dst = rep4 + (size_t)(half * BH) * TOT4 + row_off;
#pragma unroll 8
    for (int b = 0; b < BH; b++) {
        __stcs(dst, v);
        dst += TOT4;
    }

    if (half != 0) return;

    // EMA + L2 normalize for new_mem[c].
    float4 y;
    y.x = m.x * (1.f - ALPHA) + v.x * ALPHA;
    y.y = m.y * (1.f - ALPHA) + v.y * ALPHA;
    y.z = m.z * (1.f - ALPHA) + v.z * ALPHA;
    y.w = m.w * (1.f - ALPHA) + v.w * ALPHA;
    float ss = y.x * y.x + y.y * y.y + y.z * y.z + y.w * y.w;

#pragma unroll
    for (int off = 16; off > 0; off >>= 1)
        ss += __shfl_xor_sync(0xffffffffu, ss, off);
    if ((t & 31) == 0) s_red[t >> 5] = ss;
    __syncthreads();
    if (t < 32) {
        float u = (t < 16) ? s_red[t] : 0.f;
#pragma unroll
        for (int off = 8; off > 0; off >>= 1)
            u += __shfl_xor_sync(0xffffffffu, u, off);
        if (t == 0) s_red[0] = u;
    }
    __syncthreads();

    const float inv = 1.f / (sqrtf(s_red[0]) + EPS);
    y.x *= inv; y.y *= inv; y.z *= inv; y.w *= inv;
    nm4[row_off] = y;
}

extern "C" void kernel_launch(void* const* d_in, const int* in_sizes, int n_in,
                              void* d_out, int out_size) {
    const float* x = (const float*)d_in[0];
    const int* cls = (const int*)d_in[1];
    const float* memory = (const float*)d_in[2];
    float* out = (float*)d_out;

    float* sel = out;                    // [B, D]
    float* rep = out + (size_t)B * D;    // [B, C, D]
    float* nm = rep + (size_t)B * C * D; // [C, D]

    dim3 grid(C, 2);
    fused_kernel<<<grid, 512>>>((const float4*)x, (const float4*)memory, cls,
                                (float4*)sel, (float4*)rep, (float4*)nm);
}